// round 8
// baseline (speedup 1.0000x reference)
#include <cuda_runtime.h>
#include <math_constants.h>

// Problem constants
#define Bb 2
#define Ss 4096
#define Hh 8
#define HDv 512   // H*D (D=64)

typedef unsigned long long ull;
typedef unsigned int u32;

// Scratch (device globals; no allocation allowed)
__device__ float Qg[Bb * Ss * HDv];
__device__ float Kg[Bb * Ss * HDv];
__device__ float Vg[Bb * Ss * HDv];
__device__ float Og[Bb * Ss * HDv];

// ---- helpers --------------------------------------------------------------
__device__ __forceinline__ ull pk2(float a, float b) {
    ull r; asm("mov.b64 %0, {%1, %2};" : "=l"(r) : "f"(a), "f"(b)); return r;
}
__device__ __forceinline__ void upk(ull v, float& a, float& b) {
    asm("mov.b64 {%0, %1}, %2;" : "=f"(a), "=f"(b) : "l"(v));
}
__device__ __forceinline__ ull f2fma(ull a, ull b, ull c) {
    ull d; asm("fma.rn.f32x2 %0, %1, %2, %3;" : "=l"(d) : "l"(a), "l"(b), "l"(c));
    return d;
}
__device__ __forceinline__ u32 to_tf32(float f) {
    u32 r; asm("cvt.rna.tf32.f32 %0, %1;" : "=r"(r) : "f"(f)); return r;
}
__device__ __forceinline__ void mma_tf32(
    float& d0, float& d1, float& d2, float& d3,
    u32 a0, u32 a1, u32 a2, u32 a3, u32 b0, u32 b1)
{
    asm("mma.sync.aligned.m16n8k8.row.col.f32.tf32.tf32.f32 "
        "{%0,%1,%2,%3}, {%4,%5,%6,%7}, {%8,%9}, {%0,%1,%2,%3};"
        : "+f"(d0), "+f"(d1), "+f"(d2), "+f"(d3)
        : "r"(a0), "r"(a1), "r"(a2), "r"(a3), "r"(b0), "r"(b1));
}
__device__ __forceinline__ void cpa16(u32 dst, const void* src) {
    asm volatile("cp.async.cg.shared.global [%0], [%1], 16;"
                 :: "r"(dst), "l"(src) : "memory");
}
__device__ __forceinline__ void cpa_commit() {
    asm volatile("cp.async.commit_group;" ::: "memory");
}
__device__ __forceinline__ void cpa_wait1() {
    asm volatile("cp.async.wait_group 1;" ::: "memory");
}

// ---------------------------------------------------------------------------
// tf32 GEMM for QKV projections (fused over grid.z): C = A[M,512] @ W[512,512].
// Epilogue stores tf32-ROUNDED floats (flash consumes raw bits).
// ---------------------------------------------------------------------------
#define LDA 36
#define LDB 136

__global__ __launch_bounds__(256) void gemm_qkv_tf32(
    const float* __restrict__ A0, const float* __restrict__ A1,
    const float* __restrict__ A2,
    const float* __restrict__ W0, const float* __restrict__ W1,
    const float* __restrict__ W2,
    float* __restrict__ C0, float* __restrict__ C1, float* __restrict__ C2)
{
    __shared__ u32 As[128 * LDA];
    __shared__ u32 Bs[32 * LDB];

    const float* A; const float* Bw; float* C;
    if (blockIdx.z == 0)      { A = A0; Bw = W0; C = C0; }
    else if (blockIdx.z == 1) { A = A1; Bw = W1; C = C1; }
    else                      { A = A2; Bw = W2; C = C2; }

    const int tid  = threadIdx.x;
    const int lane = tid & 31;
    const int w    = tid >> 5;
    const int g    = lane >> 2;
    const int c    = lane & 3;
    const int wm   = w & 3;
    const int wn   = w >> 2;
    const int bn = blockIdx.x * 128;
    const int bm = blockIdx.y * 128;

    const int arow = tid >> 1;
    const int akg  = (tid & 1) * 16;
    const int brow = tid >> 3;
    const int bcg  = (tid & 7) * 16;

    float acc[2][8][4];
#pragma unroll
    for (int mt = 0; mt < 2; ++mt)
#pragma unroll
        for (int nt = 0; nt < 8; ++nt)
#pragma unroll
            for (int j = 0; j < 4; ++j) acc[mt][nt][j] = 0.f;

    for (int k0 = 0; k0 < 512; k0 += 32) {
        {
            const float* Ap = A + (size_t)(bm + arow) * 512 + k0 + akg;
#pragma unroll
            for (int i = 0; i < 4; ++i) {
                float4 v = *(const float4*)(Ap + 4 * i);
                *(uint4*)&As[arow * LDA + akg + 4 * i] =
                    make_uint4(to_tf32(v.x), to_tf32(v.y), to_tf32(v.z), to_tf32(v.w));
            }
        }
        {
            const float* Bp = Bw + (size_t)(k0 + brow) * 512 + bn + bcg;
#pragma unroll
            for (int i = 0; i < 4; ++i) {
                float4 v = *(const float4*)(Bp + 4 * i);
                *(uint4*)&Bs[brow * LDB + bcg + 4 * i] =
                    make_uint4(to_tf32(v.x), to_tf32(v.y), to_tf32(v.z), to_tf32(v.w));
            }
        }
        __syncthreads();

#pragma unroll
        for (int ks = 0; ks < 4; ++ks) {
            u32 a[2][4];
#pragma unroll
            for (int mt = 0; mt < 2; ++mt) {
                int base = (32 * wm + 16 * mt + g) * LDA + ks * 8 + c;
                a[mt][0] = As[base];
                a[mt][1] = As[base + 8 * LDA];
                a[mt][2] = As[base + 4];
                a[mt][3] = As[base + 8 * LDA + 4];
            }
#pragma unroll
            for (int nt = 0; nt < 8; ++nt) {
                u32 b0 = Bs[(ks * 8 + c)     * LDB + 64 * wn + nt * 8 + g];
                u32 b1 = Bs[(ks * 8 + c + 4) * LDB + 64 * wn + nt * 8 + g];
#pragma unroll
                for (int mt = 0; mt < 2; ++mt)
                    mma_tf32(acc[mt][nt][0], acc[mt][nt][1], acc[mt][nt][2], acc[mt][nt][3],
                             a[mt][0], a[mt][1], a[mt][2], a[mt][3], b0, b1);
            }
        }
        __syncthreads();
    }

#pragma unroll
    for (int mt = 0; mt < 2; ++mt) {
        float* Cp0 = C + (size_t)(bm + 32 * wm + 16 * mt + g) * 512 + bn + 64 * wn;
        float* Cp1 = Cp0 + (size_t)8 * 512;
#pragma unroll
        for (int nt = 0; nt < 8; ++nt) {
            *(uint2*)(Cp0 + nt * 8 + 2 * c) =
                make_uint2(to_tf32(acc[mt][nt][0]), to_tf32(acc[mt][nt][1]));
            *(uint2*)(Cp1 + nt * 8 + 2 * c) =
                make_uint2(to_tf32(acc[mt][nt][2]), to_tf32(acc[mt][nt][3]));
        }
    }
}

// ---------------------------------------------------------------------------
// SGEMM fp32 (FFMA2) — final Wo projection (accuracy margin).
// ---------------------------------------------------------------------------
__global__ __launch_bounds__(256) void sgemm_k512(
    const float* __restrict__ A, const float* __restrict__ Bw,
    float* __restrict__ C)
{
    __shared__ float Asf[8][128];
    __shared__ float Bsf[8][128];

    const int tid = threadIdx.x;
    const int tx = tid & 15;
    const int ty = tid >> 4;
    const int bn = blockIdx.x * 128;
    const int bm = blockIdx.y * 128;

    const int arow = tid >> 1;
    const int acol = (tid & 1) << 2;
    const int brow = tid >> 5;
    const int bcol = (tid & 31) << 2;

    const float* Ap = A + (size_t)(bm + arow) * 512 + acol;
    const float* Bp = Bw + (size_t)brow * 512 + bn + bcol;

    ull acc2[8][4];
#pragma unroll
    for (int i = 0; i < 8; ++i)
#pragma unroll
        for (int j = 0; j < 4; ++j) acc2[i][j] = 0ull;

    for (int k0 = 0; k0 < 512; k0 += 8) {
        float4 av = *(const float4*)Ap;  Ap += 8;
        float4 bv = *(const float4*)Bp;  Bp += 8 * 512;
        Asf[acol + 0][arow] = av.x;
        Asf[acol + 1][arow] = av.y;
        Asf[acol + 2][arow] = av.z;
        Asf[acol + 3][arow] = av.w;
        *(float4*)&Bsf[brow][bcol] = bv;
        __syncthreads();
#pragma unroll
        for (int kk = 0; kk < 8; ++kk) {
            float ar[8];
            *(float4*)(ar)     = *(const float4*)&Asf[kk][ty * 8];
            *(float4*)(ar + 4) = *(const float4*)&Asf[kk][ty * 8 + 4];
            ulonglong2 b01 = *(const ulonglong2*)&Bsf[kk][tx * 8];
            ulonglong2 b23 = *(const ulonglong2*)&Bsf[kk][tx * 8 + 4];
#pragma unroll
            for (int i = 0; i < 8; ++i) {
                ull ap = pk2(ar[i], ar[i]);
                acc2[i][0] = f2fma(ap, b01.x, acc2[i][0]);
                acc2[i][1] = f2fma(ap, b01.y, acc2[i][1]);
                acc2[i][2] = f2fma(ap, b23.x, acc2[i][2]);
                acc2[i][3] = f2fma(ap, b23.y, acc2[i][3]);
            }
        }
        __syncthreads();
    }

    float* Cp = C + (size_t)(bm + ty * 8) * 512 + bn + tx * 8;
#pragma unroll
    for (int i = 0; i < 8; ++i) {
        float c0, c1, c2, c3, c4, c5, c6, c7;
        upk(acc2[i][0], c0, c1); upk(acc2[i][1], c2, c3);
        upk(acc2[i][2], c4, c5); upk(acc2[i][3], c6, c7);
        *(float4*)(Cp + (size_t)i * 512)     = make_float4(c0, c1, c2, c3);
        *(float4*)(Cp + (size_t)i * 512 + 4) = make_float4(c4, c5, c6, c7);
    }
}

// ---------------------------------------------------------------------------
// Flash attention v7:
//  - tf32 mma, Bq=128, 128 threads = 4 warps m32n64
//  - K stored with per-8-group column permutation slot(k)=((k&3)<<1)|(k>>2):
//    S accumulator regs ARE the PV A-fragments (no shuffles); V unpermuted.
//  - cp.async double-buffered K/V (latency off critical path)
//  - full mask tile prefetched into registers at iteration top
// smem: Qs[128][68] | Kbuf[2][64][68] | Vbuf[2][64][72] = 106496 B -> 2 CTAs/SM
// ---------------------------------------------------------------------------
#define LDQ 68
#define LDK 68
#define LDV 72
#define QW   (128 * LDQ)         // 8704 u32
#define KBW  (64 * LDK)          // 4352 u32
#define VBW  (64 * LDV)          // 4608 u32
#define KOFF QW                  // u32 offset of Kbuf0
#define VOFF (QW + 2 * KBW)      // u32 offset of Vbuf0
#define FSMEM ((QW + 2 * KBW + 2 * VBW) * 4)   // 106496 B

__global__ void __launch_bounds__(128, 2) flash_attn(
    const float* __restrict__ Q, const float* __restrict__ K,
    const float* __restrict__ V, const int* __restrict__ Mask,
    float* __restrict__ O)
{
    extern __shared__ u32 dsm[];
    u32* Qs = dsm;
    const u32 sbase = (u32)__cvta_generic_to_shared(dsm);

    const int tid  = threadIdx.x;
    const int lane = tid & 31;
    const int w    = tid >> 5;
    const int g    = lane >> 2;
    const int c    = lane & 3;
    const int q0 = blockIdx.x * 128;
    const int h  = blockIdx.y;
    const int b  = blockIdx.z;

    const int r    = tid >> 1;           // 0..63 coop-load row
    const int half = (tid & 1) * 32;
    // permuted K row slot within its 8-group
    const int prow = (r & 56) | (((r & 3) << 1) | ((r & 7) >> 2));

    const float* ksrc0 = K + ((size_t)(b * Ss + r)) * HDv + h * 64 + half;
    const float* vsrc0 = V + ((size_t)(b * Ss + r)) * HDv + h * 64 + half;
    const u32 kdst0 = sbase + (KOFF + prow * LDK + half) * 4;
    const u32 vdst0 = sbase + (VOFF + r * LDV + half) * 4;

    // Q tile: raw bit copy (already tf32-valued)
    {
        const float* qp = Q + (size_t)(b * Ss + q0 + tid) * HDv + h * 64;
#pragma unroll
        for (int i = 0; i < 16; ++i)
            *(uint4*)&Qs[tid * LDQ + 4 * i] = *(const uint4*)(qp + 4 * i);
    }

    // issue K/V tile 0 into buffer 0
    {
        const float* kp = ksrc0;
        const float* vp = vsrc0;
#pragma unroll
        for (int j = 0; j < 8; ++j) {
            cpa16(kdst0 + 16 * j, kp + 4 * j);
            cpa16(vdst0 + 16 * j, vp + 4 * j);
        }
        cpa_commit();
    }

    float m_[2][2], l_[2][2];
    float o[2][8][4];
#pragma unroll
    for (int mt = 0; mt < 2; ++mt) {
#pragma unroll
        for (int sb = 0; sb < 2; ++sb) { m_[mt][sb] = -CUDART_INF_F; l_[mt][sb] = 0.f; }
#pragma unroll
        for (int nt = 0; nt < 8; ++nt)
#pragma unroll
            for (int j = 0; j < 4; ++j) o[mt][nt][j] = 0.f;
    }

    const int* Mbase = Mask + ((size_t)(b * Hh + h) * Ss + q0 + 32 * w + g) * Ss;

    for (int it = 0; it < Ss / 64; ++it) {
        const int cur = it & 1;

        // 1. prefetch next K/V tile into the other buffer
        if (it + 1 < Ss / 64) {
            const float* kp = ksrc0 + (size_t)(it + 1) * 64 * HDv;
            const float* vp = vsrc0 + (size_t)(it + 1) * 64 * HDv;
            const u32 kd = kdst0 + (cur ^ 1) * KBW * 4;
            const u32 vd = vdst0 + (cur ^ 1) * VBW * 4;
#pragma unroll
            for (int j = 0; j < 8; ++j) {
                cpa16(kd + 16 * j, kp + 4 * j);
                cpa16(vd + 16 * j, vp + 4 * j);
            }
        }
        cpa_commit();

        // 2. prefetch mask tile into registers (consumed ~800 cyc later)
        int msk[2][2][16];
        {
            const int k0 = it * 64;
#pragma unroll
            for (int mt = 0; mt < 2; ++mt)
#pragma unroll
                for (int sb = 0; sb < 2; ++sb) {
                    const int* p = Mbase + (size_t)(16 * mt + 8 * sb) * Ss + k0 + c;
#pragma unroll
                    for (int nt = 0; nt < 8; ++nt) {
                        msk[mt][sb][2 * nt]     = p[nt * 8];
                        msk[mt][sb][2 * nt + 1] = p[nt * 8 + 4];
                    }
                }
        }

        // 3. wait for current tile, make visible
        cpa_wait1();
        __syncthreads();

        const u32* Kc = dsm + KOFF + cur * KBW;
        const u32* Vc = dsm + VOFF + cur * VBW;

        // ---- S = Q K^T (columns in permuted slot order) ----
        float s[2][8][4];
#pragma unroll
        for (int mt = 0; mt < 2; ++mt)
#pragma unroll
            for (int nt = 0; nt < 8; ++nt)
#pragma unroll
                for (int j = 0; j < 4; ++j) s[mt][nt][j] = 0.f;

#pragma unroll
        for (int ks = 0; ks < 8; ++ks) {
            u32 a[2][4];
#pragma unroll
            for (int mt = 0; mt < 2; ++mt) {
                int base = (32 * w + 16 * mt + g) * LDQ + ks * 8 + c;
                a[mt][0] = Qs[base];
                a[mt][1] = Qs[base + 8 * LDQ];
                a[mt][2] = Qs[base + 4];
                a[mt][3] = Qs[base + 8 * LDQ + 4];
            }
#pragma unroll
            for (int nt = 0; nt < 8; ++nt) {
                u32 b0 = Kc[(nt * 8 + g) * LDK + ks * 8 + c];
                u32 b1 = Kc[(nt * 8 + g) * LDK + ks * 8 + c + 4];
#pragma unroll
                for (int mt = 0; mt < 2; ++mt)
                    mma_tf32(s[mt][nt][0], s[mt][nt][1], s[mt][nt][2], s[mt][nt][3],
                             a[mt][0], a[mt][1], a[mt][2], a[mt][3], b0, b1);
            }
        }

        // ---- online softmax; P (tf32-rounded) stays in s[] ----
        // accumulator (row, slot 2c/2c+1) == true k = c / c+4 by construction
#pragma unroll
        for (int mt = 0; mt < 2; ++mt)
#pragma unroll
        for (int sb = 0; sb < 2; ++sb) {
            const int j0 = 2 * sb, j1 = 2 * sb + 1;
            float mt_ = -CUDART_INF_F;
#pragma unroll
            for (int nt = 0; nt < 8; ++nt) {
                s[mt][nt][j0] = (msk[mt][sb][2 * nt]     != 0) ? -1e10f : s[mt][nt][j0] * 0.125f;
                s[mt][nt][j1] = (msk[mt][sb][2 * nt + 1] != 0) ? -1e10f : s[mt][nt][j1] * 0.125f;
                mt_ = fmaxf(mt_, fmaxf(s[mt][nt][j0], s[mt][nt][j1]));
            }
            mt_ = fmaxf(mt_, __shfl_xor_sync(0xffffffffu, mt_, 1));
            mt_ = fmaxf(mt_, __shfl_xor_sync(0xffffffffu, mt_, 2));
            float mnew = fmaxf(m_[mt][sb], mt_);
            float corr = __expf(m_[mt][sb] - mnew);
            m_[mt][sb] = mnew;
            float rs = 0.f;
#pragma unroll
            for (int nt = 0; nt < 8; ++nt) {
                float p0 = __uint_as_float(to_tf32(__expf(s[mt][nt][j0] - mnew)));
                float p1 = __uint_as_float(to_tf32(__expf(s[mt][nt][j1] - mnew)));
                rs += p0 + p1;
                s[mt][nt][j0] = p0;
                s[mt][nt][j1] = p1;
                o[mt][nt][j0] *= corr;
                o[mt][nt][j1] *= corr;
            }
            rs += __shfl_xor_sync(0xffffffffu, rs, 1);
            rs += __shfl_xor_sync(0xffffffffu, rs, 2);
            l_[mt][sb] = l_[mt][sb] * corr + rs;
        }

        // ---- O += P V : A-fragments straight from s[] (permutation magic) ----
#pragma unroll
        for (int kc = 0; kc < 8; ++kc) {
#pragma unroll
            for (int nt = 0; nt < 8; ++nt) {
                u32 b0 = Vc[(kc * 8 + c)     * LDV + nt * 8 + g];
                u32 b1 = Vc[(kc * 8 + c + 4) * LDV + nt * 8 + g];
#pragma unroll
                for (int mt = 0; mt < 2; ++mt)
                    mma_tf32(o[mt][nt][0], o[mt][nt][1], o[mt][nt][2], o[mt][nt][3],
                             __float_as_uint(s[mt][kc][0]), __float_as_uint(s[mt][kc][2]),
                             __float_as_uint(s[mt][kc][1]), __float_as_uint(s[mt][kc][3]),
                             b0, b1);
            }
        }

        __syncthreads();  // PV reads done before next iter's cp.async overwrites
    }

    // normalize + write
#pragma unroll
    for (int mt = 0; mt < 2; ++mt) {
        const float inv0 = 1.f / l_[mt][0];
        const float inv1 = 1.f / l_[mt][1];
        float* op0 = O + (size_t)(b * Ss + q0 + 32 * w + 16 * mt + g) * HDv + h * 64;
        float* op1 = op0 + (size_t)8 * HDv;
#pragma unroll
        for (int nt = 0; nt < 8; ++nt) {
            *(float2*)(op0 + nt * 8 + 2 * c) =
                make_float2(o[mt][nt][0] * inv0, o[mt][nt][1] * inv0);
            *(float2*)(op1 + nt * 8 + 2 * c) =
                make_float2(o[mt][nt][2] * inv1, o[mt][nt][3] * inv1);
        }
    }
}

// ---------------------------------------------------------------------------
// Launch
// ---------------------------------------------------------------------------
extern "C" void kernel_launch(void* const* d_in, const int* in_sizes, int n_in,
                              void* d_out, int out_size)
{
    (void)in_sizes; (void)n_in; (void)out_size;
    const float* queries = (const float*)d_in[0];
    const float* keys    = (const float*)d_in[1];
    const float* values  = (const float*)d_in[2];
    const int*   mask    = (const int*)d_in[3];
    const float* Wq = (const float*)d_in[4];
    const float* Wk = (const float*)d_in[5];
    const float* Wv = (const float*)d_in[6];
    const float* Wo = (const float*)d_in[7];

    void *qp, *kp, *vp, *op;
    cudaGetSymbolAddress(&qp, Qg);
    cudaGetSymbolAddress(&kp, Kg);
    cudaGetSymbolAddress(&vp, Vg);
    cudaGetSymbolAddress(&op, Og);

    cudaFuncSetAttribute(flash_attn,
                         cudaFuncAttributeMaxDynamicSharedMemorySize, FSMEM);

    dim3 gg(512 / 128, (Bb * Ss) / 128);        // (4, 64)
    dim3 gq(512 / 128, (Bb * Ss) / 128, 3);     // fused QKV

    gemm_qkv_tf32<<<gq, 256>>>(queries, keys, values, Wq, Wk, Wv,
                               (float*)qp, (float*)kp, (float*)vp);

    flash_attn<<<dim3(Ss / 128, Hh, Bb), 128, FSMEM>>>(
        (const float*)qp, (const float*)kp, (const float*)vp, mask, (float*)op);

    sgemm_k512<<<gg, 256>>>((const float*)op, Wo, (float*)d_out);
}

// round 9
// speedup vs baseline: 1.1944x; 1.1944x over previous
#include <cuda_runtime.h>
#include <math_constants.h>

// Problem constants
#define Bb 2
#define Ss 4096
#define Hh 8
#define HDv 512   // H*D (D=64)

typedef unsigned long long ull;
typedef unsigned int u32;

// Scratch (device globals; no allocation allowed)
__device__ float Qg[Bb * Ss * HDv];
__device__ float Kg[Bb * Ss * HDv];
__device__ float Vg[Bb * Ss * HDv];
__device__ float Og[Bb * Ss * HDv];

// ---- helpers --------------------------------------------------------------
__device__ __forceinline__ ull pk2(float a, float b) {
    ull r; asm("mov.b64 %0, {%1, %2};" : "=l"(r) : "f"(a), "f"(b)); return r;
}
__device__ __forceinline__ void upk(ull v, float& a, float& b) {
    asm("mov.b64 {%0, %1}, %2;" : "=f"(a), "=f"(b) : "l"(v));
}
__device__ __forceinline__ ull f2fma(ull a, ull b, ull c) {
    ull d; asm("fma.rn.f32x2 %0, %1, %2, %3;" : "=l"(d) : "l"(a), "l"(b), "l"(c));
    return d;
}
__device__ __forceinline__ u32 to_tf32(float f) {
    u32 r; asm("cvt.rna.tf32.f32 %0, %1;" : "=r"(r) : "f"(f)); return r;
}
__device__ __forceinline__ void mma_tf32(
    float& d0, float& d1, float& d2, float& d3,
    u32 a0, u32 a1, u32 a2, u32 a3, u32 b0, u32 b1)
{
    asm("mma.sync.aligned.m16n8k8.row.col.f32.tf32.tf32.f32 "
        "{%0,%1,%2,%3}, {%4,%5,%6,%7}, {%8,%9}, {%0,%1,%2,%3};"
        : "+f"(d0), "+f"(d1), "+f"(d2), "+f"(d3)
        : "r"(a0), "r"(a1), "r"(a2), "r"(a3), "r"(b0), "r"(b1));
}
__device__ __forceinline__ void cpa16(u32 dst, const void* src) {
    asm volatile("cp.async.cg.shared.global [%0], [%1], 16;"
                 :: "r"(dst), "l"(src) : "memory");
}
__device__ __forceinline__ void cpa_commit() {
    asm volatile("cp.async.commit_group;" ::: "memory");
}
__device__ __forceinline__ void cpa_wait0() {
    asm volatile("cp.async.wait_group 0;" ::: "memory");
}

// ---------------------------------------------------------------------------
// tf32 GEMM for QKV projections (fused over grid.z): C = A[M,512] @ W[512,512].
// Epilogue stores tf32-ROUNDED floats (flash consumes raw bits).
// ---------------------------------------------------------------------------
#define LDA 36
#define LDB 136

__global__ __launch_bounds__(256) void gemm_qkv_tf32(
    const float* __restrict__ A0, const float* __restrict__ A1,
    const float* __restrict__ A2,
    const float* __restrict__ W0, const float* __restrict__ W1,
    const float* __restrict__ W2,
    float* __restrict__ C0, float* __restrict__ C1, float* __restrict__ C2)
{
    __shared__ u32 As[128 * LDA];
    __shared__ u32 Bs[32 * LDB];

    const float* A; const float* Bw; float* C;
    if (blockIdx.z == 0)      { A = A0; Bw = W0; C = C0; }
    else if (blockIdx.z == 1) { A = A1; Bw = W1; C = C1; }
    else                      { A = A2; Bw = W2; C = C2; }

    const int tid  = threadIdx.x;
    const int lane = tid & 31;
    const int w    = tid >> 5;
    const int g    = lane >> 2;
    const int c    = lane & 3;
    const int wm   = w & 3;
    const int wn   = w >> 2;
    const int bn = blockIdx.x * 128;
    const int bm = blockIdx.y * 128;

    const int arow = tid >> 1;
    const int akg  = (tid & 1) * 16;
    const int brow = tid >> 3;
    const int bcg  = (tid & 7) * 16;

    float acc[2][8][4];
#pragma unroll
    for (int mt = 0; mt < 2; ++mt)
#pragma unroll
        for (int nt = 0; nt < 8; ++nt)
#pragma unroll
            for (int j = 0; j < 4; ++j) acc[mt][nt][j] = 0.f;

    for (int k0 = 0; k0 < 512; k0 += 32) {
        {
            const float* Ap = A + (size_t)(bm + arow) * 512 + k0 + akg;
#pragma unroll
            for (int i = 0; i < 4; ++i) {
                float4 v = *(const float4*)(Ap + 4 * i);
                *(uint4*)&As[arow * LDA + akg + 4 * i] =
                    make_uint4(to_tf32(v.x), to_tf32(v.y), to_tf32(v.z), to_tf32(v.w));
            }
        }
        {
            const float* Bp = Bw + (size_t)(k0 + brow) * 512 + bn + bcg;
#pragma unroll
            for (int i = 0; i < 4; ++i) {
                float4 v = *(const float4*)(Bp + 4 * i);
                *(uint4*)&Bs[brow * LDB + bcg + 4 * i] =
                    make_uint4(to_tf32(v.x), to_tf32(v.y), to_tf32(v.z), to_tf32(v.w));
            }
        }
        __syncthreads();

#pragma unroll
        for (int ks = 0; ks < 4; ++ks) {
            u32 a[2][4];
#pragma unroll
            for (int mt = 0; mt < 2; ++mt) {
                int base = (32 * wm + 16 * mt + g) * LDA + ks * 8 + c;
                a[mt][0] = As[base];
                a[mt][1] = As[base + 8 * LDA];
                a[mt][2] = As[base + 4];
                a[mt][3] = As[base + 8 * LDA + 4];
            }
#pragma unroll
            for (int nt = 0; nt < 8; ++nt) {
                u32 b0 = Bs[(ks * 8 + c)     * LDB + 64 * wn + nt * 8 + g];
                u32 b1 = Bs[(ks * 8 + c + 4) * LDB + 64 * wn + nt * 8 + g];
#pragma unroll
                for (int mt = 0; mt < 2; ++mt)
                    mma_tf32(acc[mt][nt][0], acc[mt][nt][1], acc[mt][nt][2], acc[mt][nt][3],
                             a[mt][0], a[mt][1], a[mt][2], a[mt][3], b0, b1);
            }
        }
        __syncthreads();
    }

#pragma unroll
    for (int mt = 0; mt < 2; ++mt) {
        float* Cp0 = C + (size_t)(bm + 32 * wm + 16 * mt + g) * 512 + bn + 64 * wn;
        float* Cp1 = Cp0 + (size_t)8 * 512;
#pragma unroll
        for (int nt = 0; nt < 8; ++nt) {
            *(uint2*)(Cp0 + nt * 8 + 2 * c) =
                make_uint2(to_tf32(acc[mt][nt][0]), to_tf32(acc[mt][nt][1]));
            *(uint2*)(Cp1 + nt * 8 + 2 * c) =
                make_uint2(to_tf32(acc[mt][nt][2]), to_tf32(acc[mt][nt][3]));
        }
    }
}

// ---------------------------------------------------------------------------
// SGEMM fp32 (FFMA2) — final Wo projection (accuracy margin).
// ---------------------------------------------------------------------------
__global__ __launch_bounds__(256) void sgemm_k512(
    const float* __restrict__ A, const float* __restrict__ Bw,
    float* __restrict__ C)
{
    __shared__ float Asf[8][128];
    __shared__ float Bsf[8][128];

    const int tid = threadIdx.x;
    const int tx = tid & 15;
    const int ty = tid >> 4;
    const int bn = blockIdx.x * 128;
    const int bm = blockIdx.y * 128;

    const int arow = tid >> 1;
    const int acol = (tid & 1) << 2;
    const int brow = tid >> 5;
    const int bcol = (tid & 31) << 2;

    const float* Ap = A + (size_t)(bm + arow) * 512 + acol;
    const float* Bp = Bw + (size_t)brow * 512 + bn + bcol;

    ull acc2[8][4];
#pragma unroll
    for (int i = 0; i < 8; ++i)
#pragma unroll
        for (int j = 0; j < 4; ++j) acc2[i][j] = 0ull;

    for (int k0 = 0; k0 < 512; k0 += 8) {
        float4 av = *(const float4*)Ap;  Ap += 8;
        float4 bv = *(const float4*)Bp;  Bp += 8 * 512;
        Asf[acol + 0][arow] = av.x;
        Asf[acol + 1][arow] = av.y;
        Asf[acol + 2][arow] = av.z;
        Asf[acol + 3][arow] = av.w;
        *(float4*)&Bsf[brow][bcol] = bv;
        __syncthreads();
#pragma unroll
        for (int kk = 0; kk < 8; ++kk) {
            float ar[8];
            *(float4*)(ar)     = *(const float4*)&Asf[kk][ty * 8];
            *(float4*)(ar + 4) = *(const float4*)&Asf[kk][ty * 8 + 4];
            ulonglong2 b01 = *(const ulonglong2*)&Bsf[kk][tx * 8];
            ulonglong2 b23 = *(const ulonglong2*)&Bsf[kk][tx * 8 + 4];
#pragma unroll
            for (int i = 0; i < 8; ++i) {
                ull ap = pk2(ar[i], ar[i]);
                acc2[i][0] = f2fma(ap, b01.x, acc2[i][0]);
                acc2[i][1] = f2fma(ap, b01.y, acc2[i][1]);
                acc2[i][2] = f2fma(ap, b23.x, acc2[i][2]);
                acc2[i][3] = f2fma(ap, b23.y, acc2[i][3]);
            }
        }
        __syncthreads();
    }

    float* Cp = C + (size_t)(bm + ty * 8) * 512 + bn + tx * 8;
#pragma unroll
    for (int i = 0; i < 8; ++i) {
        float c0, c1, c2, c3, c4, c5, c6, c7;
        upk(acc2[i][0], c0, c1); upk(acc2[i][1], c2, c3);
        upk(acc2[i][2], c4, c5); upk(acc2[i][3], c6, c7);
        *(float4*)(Cp + (size_t)i * 512)     = make_float4(c0, c1, c2, c3);
        *(float4*)(Cp + (size_t)i * 512 + 4) = make_float4(c4, c5, c6, c7);
    }
}

// ---------------------------------------------------------------------------
// Flash attention v9:
//  - tf32 mma, Bq=128, 128 threads = 4 warps m32n64
//  - permuted K (slot(k) = ((k&3)<<1)|(k>>2) within 8-groups): S accumulator
//    registers ARE the PV A-fragments (verified in v8) -> zero shuffles
//  - V natural [k][d] (LDV=72): B-fragment read V[k][n], conflict-free,
//    no transpose on store
//  - mask prefetched at iter top, BIT-PACKED to 4 registers (no spills)
//  - single-buffered K/V via cp.async (3 CTAs/SM for latency hiding)
// smem: Qs[128][68] + Ks[64][68] + Vs[64][72] = 70656 B
// ---------------------------------------------------------------------------
#define LDQ 68
#define LDK 68
#define LDV 72
#define QW   (128 * LDQ)
#define KBW  (64 * LDK)
#define KOFF QW
#define VOFF (QW + KBW)
#define FSMEM ((QW + KBW + 64 * LDV) * 4)   // 70656 B

__global__ void __launch_bounds__(128, 3) flash_attn(
    const float* __restrict__ Q, const float* __restrict__ K,
    const float* __restrict__ V, const int* __restrict__ Mask,
    float* __restrict__ O)
{
    extern __shared__ u32 dsm[];
    u32* Qs = dsm;
    u32* Ks = dsm + KOFF;
    u32* Vs = dsm + VOFF;
    const u32 sbase = (u32)__cvta_generic_to_shared(dsm);

    const int tid  = threadIdx.x;
    const int lane = tid & 31;
    const int w    = tid >> 5;
    const int g    = lane >> 2;
    const int c    = lane & 3;
    const int q0 = blockIdx.x * 128;
    const int h  = blockIdx.y;
    const int b  = blockIdx.z;

    const int r    = tid >> 1;           // 0..63 coop-load row
    const int half = (tid & 1) * 32;
    // permuted K row slot within its 8-group
    const int prow = (r & 56) | (((r & 3) << 1) | ((r & 7) >> 2));

    const float* ksrc0 = K + ((size_t)(b * Ss + r)) * HDv + h * 64 + half;
    const float* vsrc0 = V + ((size_t)(b * Ss + r)) * HDv + h * 64 + half;
    const u32 kdst = sbase + (KOFF + prow * LDK + half) * 4;
    const u32 vdst = sbase + (VOFF + r * LDV + half) * 4;

    // Q tile: raw bit copy (already tf32-valued)
    {
        const float* qp = Q + (size_t)(b * Ss + q0 + tid) * HDv + h * 64;
#pragma unroll
        for (int i = 0; i < 16; ++i)
            *(uint4*)&Qs[tid * LDQ + 4 * i] = *(const uint4*)(qp + 4 * i);
    }

    float m_[2][2], l_[2][2];
    float o[2][8][4];
#pragma unroll
    for (int mt = 0; mt < 2; ++mt) {
#pragma unroll
        for (int sb = 0; sb < 2; ++sb) { m_[mt][sb] = -CUDART_INF_F; l_[mt][sb] = 0.f; }
#pragma unroll
        for (int nt = 0; nt < 8; ++nt)
#pragma unroll
            for (int j = 0; j < 4; ++j) o[mt][nt][j] = 0.f;
    }

    const int* Mbase = Mask + ((size_t)(b * Hh + h) * Ss + q0 + 32 * w + g) * Ss;

    for (int it = 0; it < Ss / 64; ++it) {
        __syncthreads();  // Ks/Vs free (prev QK/PV done); covers Q store iter 0

        // 1. fill K (permuted) and V (natural) via cp.async
        {
            const float* kp = ksrc0 + (size_t)it * 64 * HDv;
            const float* vp = vsrc0 + (size_t)it * 64 * HDv;
#pragma unroll
            for (int j = 0; j < 8; ++j) {
                cpa16(kdst + 16 * j, kp + 4 * j);
                cpa16(vdst + 16 * j, vp + 4 * j);
            }
            cpa_commit();
        }

        // 2. mask prefetch, bit-packed: bit(2nt)=col nt*8+c, bit(2nt+1)=col nt*8+c+4
        u32 mbits[2][2];
        {
            const int k0 = it * 64;
#pragma unroll
            for (int mt = 0; mt < 2; ++mt)
#pragma unroll
                for (int sb = 0; sb < 2; ++sb) {
                    const int* p = Mbase + (size_t)(16 * mt + 8 * sb) * Ss + k0 + c;
                    u32 bits = 0;
#pragma unroll
                    for (int nt = 0; nt < 8; ++nt) {
                        if (p[nt * 8])     bits |= 1u << (2 * nt);
                        if (p[nt * 8 + 4]) bits |= 1u << (2 * nt + 1);
                    }
                    mbits[mt][sb] = bits;
                }
        }

        // 3. wait K/V, make visible
        cpa_wait0();
        __syncthreads();

        // ---- S = Q K^T (columns in permuted slot order) ----
        float s[2][8][4];
#pragma unroll
        for (int mt = 0; mt < 2; ++mt)
#pragma unroll
            for (int nt = 0; nt < 8; ++nt)
#pragma unroll
                for (int j = 0; j < 4; ++j) s[mt][nt][j] = 0.f;

#pragma unroll
        for (int ks = 0; ks < 8; ++ks) {
            u32 a[2][4];
#pragma unroll
            for (int mt = 0; mt < 2; ++mt) {
                int base = (32 * w + 16 * mt + g) * LDQ + ks * 8 + c;
                a[mt][0] = Qs[base];
                a[mt][1] = Qs[base + 8 * LDQ];
                a[mt][2] = Qs[base + 4];
                a[mt][3] = Qs[base + 8 * LDQ + 4];
            }
#pragma unroll
            for (int nt = 0; nt < 8; ++nt) {
                u32 b0 = Ks[(nt * 8 + g) * LDK + ks * 8 + c];
                u32 b1 = Ks[(nt * 8 + g) * LDK + ks * 8 + c + 4];
#pragma unroll
                for (int mt = 0; mt < 2; ++mt)
                    mma_tf32(s[mt][nt][0], s[mt][nt][1], s[mt][nt][2], s[mt][nt][3],
                             a[mt][0], a[mt][1], a[mt][2], a[mt][3], b0, b1);
            }
        }

        // ---- online softmax; P (tf32-rounded) stays in s[] ----
        // slot 2c == true k=c ; slot 2c+1 == true k=c+4 (per 8-group)
#pragma unroll
        for (int mt = 0; mt < 2; ++mt)
#pragma unroll
        for (int sb = 0; sb < 2; ++sb) {
            const int j0 = 2 * sb, j1 = 2 * sb + 1;
            const u32 bits = mbits[mt][sb];
            float mt_ = -CUDART_INF_F;
#pragma unroll
            for (int nt = 0; nt < 8; ++nt) {
                s[mt][nt][j0] = (bits & (1u << (2 * nt)))     ? -1e10f : s[mt][nt][j0] * 0.125f;
                s[mt][nt][j1] = (bits & (1u << (2 * nt + 1))) ? -1e10f : s[mt][nt][j1] * 0.125f;
                mt_ = fmaxf(mt_, fmaxf(s[mt][nt][j0], s[mt][nt][j1]));
            }
            mt_ = fmaxf(mt_, __shfl_xor_sync(0xffffffffu, mt_, 1));
            mt_ = fmaxf(mt_, __shfl_xor_sync(0xffffffffu, mt_, 2));
            float mnew = fmaxf(m_[mt][sb], mt_);
            float corr = __expf(m_[mt][sb] - mnew);
            m_[mt][sb] = mnew;
            float rs = 0.f;
#pragma unroll
            for (int nt = 0; nt < 8; ++nt) {
                float p0 = __uint_as_float(to_tf32(__expf(s[mt][nt][j0] - mnew)));
                float p1 = __uint_as_float(to_tf32(__expf(s[mt][nt][j1] - mnew)));
                rs += p0 + p1;
                s[mt][nt][j0] = p0;
                s[mt][nt][j1] = p1;
                o[mt][nt][j0] *= corr;
                o[mt][nt][j1] *= corr;
            }
            rs += __shfl_xor_sync(0xffffffffu, rs, 1);
            rs += __shfl_xor_sync(0xffffffffu, rs, 2);
            l_[mt][sb] = l_[mt][sb] * corr + rs;
        }

        // ---- O += P V : A-fragments straight from s[] ----
#pragma unroll
        for (int kc = 0; kc < 8; ++kc) {
#pragma unroll
            for (int nt = 0; nt < 8; ++nt) {
                u32 b0 = Vs[(kc * 8 + c)     * LDV + nt * 8 + g];
                u32 b1 = Vs[(kc * 8 + c + 4) * LDV + nt * 8 + g];
#pragma unroll
                for (int mt = 0; mt < 2; ++mt)
                    mma_tf32(o[mt][nt][0], o[mt][nt][1], o[mt][nt][2], o[mt][nt][3],
                             __float_as_uint(s[mt][kc][0]), __float_as_uint(s[mt][kc][2]),
                             __float_as_uint(s[mt][kc][1]), __float_as_uint(s[mt][kc][3]),
                             b0, b1);
            }
        }
    }

    // normalize + write
#pragma unroll
    for (int mt = 0; mt < 2; ++mt) {
        const float inv0 = 1.f / l_[mt][0];
        const float inv1 = 1.f / l_[mt][1];
        float* op0 = O + (size_t)(b * Ss + q0 + 32 * w + 16 * mt + g) * HDv + h * 64;
        float* op1 = op0 + (size_t)8 * HDv;
#pragma unroll
        for (int nt = 0; nt < 8; ++nt) {
            *(float2*)(op0 + nt * 8 + 2 * c) =
                make_float2(o[mt][nt][0] * inv0, o[mt][nt][1] * inv0);
            *(float2*)(op1 + nt * 8 + 2 * c) =
                make_float2(o[mt][nt][2] * inv1, o[mt][nt][3] * inv1);
        }
    }
}

// ---------------------------------------------------------------------------
// Launch
// ---------------------------------------------------------------------------
extern "C" void kernel_launch(void* const* d_in, const int* in_sizes, int n_in,
                              void* d_out, int out_size)
{
    (void)in_sizes; (void)n_in; (void)out_size;
    const float* queries = (const float*)d_in[0];
    const float* keys    = (const float*)d_in[1];
    const float* values  = (const float*)d_in[2];
    const int*   mask    = (const int*)d_in[3];
    const float* Wq = (const float*)d_in[4];
    const float* Wk = (const float*)d_in[5];
    const float* Wv = (const float*)d_in[6];
    const float* Wo = (const float*)d_in[7];

    void *qp, *kp, *vp, *op;
    cudaGetSymbolAddress(&qp, Qg);
    cudaGetSymbolAddress(&kp, Kg);
    cudaGetSymbolAddress(&vp, Vg);
    cudaGetSymbolAddress(&op, Og);

    cudaFuncSetAttribute(flash_attn,
                         cudaFuncAttributeMaxDynamicSharedMemorySize, FSMEM);

    dim3 gg(512 / 128, (Bb * Ss) / 128);        // (4, 64)
    dim3 gq(512 / 128, (Bb * Ss) / 128, 3);     // fused QKV

    gemm_qkv_tf32<<<gq, 256>>>(queries, keys, values, Wq, Wk, Wv,
                               (float*)qp, (float*)kp, (float*)vp);

    flash_attn<<<dim3(Ss / 128, Hh, Bb), 128, FSMEM>>>(
        (const float*)qp, (const float*)kp, (const float*)vp, mask, (float*)op);

    sgemm_k512<<<gg, 256>>>((const float*)op, Wo, (float*)d_out);
}

// round 10
// speedup vs baseline: 1.6377x; 1.3712x over previous
#include <cuda_runtime.h>
#include <math_constants.h>

// Problem constants
#define Bb 2
#define Ss 4096
#define Hh 8
#define HDv 512   // H*D (D=64)

typedef unsigned long long ull;
typedef unsigned int u32;

// Scratch (device globals; no allocation allowed)
__device__ float Qg[Bb * Ss * HDv];
__device__ float Kg[Bb * Ss * HDv];
__device__ float Vg[Bb * Ss * HDv];
__device__ float Og[Bb * Ss * HDv];

#define MWORDS (Bb * Hh * Ss * (Ss / 32))   // 8,388,608 u32 = 33.5 MB
__device__ u32 Mpg[MWORDS];

// ---- helpers --------------------------------------------------------------
__device__ __forceinline__ ull pk2(float a, float b) {
    ull r; asm("mov.b64 %0, {%1, %2};" : "=l"(r) : "f"(a), "f"(b)); return r;
}
__device__ __forceinline__ void upk(ull v, float& a, float& b) {
    asm("mov.b64 {%0, %1}, %2;" : "=f"(a), "=f"(b) : "l"(v));
}
__device__ __forceinline__ ull f2fma(ull a, ull b, ull c) {
    ull d; asm("fma.rn.f32x2 %0, %1, %2, %3;" : "=l"(d) : "l"(a), "l"(b), "l"(c));
    return d;
}
__device__ __forceinline__ u32 to_tf32(float f) {
    u32 r; asm("cvt.rna.tf32.f32 %0, %1;" : "=r"(r) : "f"(f)); return r;
}
__device__ __forceinline__ void mma_tf32(
    float& d0, float& d1, float& d2, float& d3,
    u32 a0, u32 a1, u32 a2, u32 a3, u32 b0, u32 b1)
{
    asm("mma.sync.aligned.m16n8k8.row.col.f32.tf32.tf32.f32 "
        "{%0,%1,%2,%3}, {%4,%5,%6,%7}, {%8,%9}, {%0,%1,%2,%3};"
        : "+f"(d0), "+f"(d1), "+f"(d2), "+f"(d3)
        : "r"(a0), "r"(a1), "r"(a2), "r"(a3), "r"(b0), "r"(b1));
}
__device__ __forceinline__ void cpa16(u32 dst, const void* src) {
    asm volatile("cp.async.cg.shared.global [%0], [%1], 16;"
                 :: "r"(dst), "l"(src) : "memory");
}
__device__ __forceinline__ void cpa_commit() {
    asm volatile("cp.async.commit_group;" ::: "memory");
}
__device__ __forceinline__ void cpa_wait1() {
    asm volatile("cp.async.wait_group 1;" ::: "memory");
}

// ---------------------------------------------------------------------------
// Mask bit-pack: int32 mask (268M elems, 1.07 GB) -> 1 bit/elem (33.5 MB).
// Each warp: coalesced 128B read, ballot, lane0 stores the u32 word.
// ---------------------------------------------------------------------------
__global__ __launch_bounds__(256) void pack_mask(const int* __restrict__ Mask)
{
    const int lane = threadIdx.x & 31;
    const int wid  = (blockIdx.x * blockDim.x + threadIdx.x) >> 5;
    const int nw   = (gridDim.x * blockDim.x) >> 5;

    for (int w0 = wid; w0 < MWORDS; w0 += 4 * nw) {
        int w1 = w0 + nw, w2 = w0 + 2 * nw, w3 = w0 + 3 * nw;
        int v0 = Mask[(size_t)w0 * 32 + lane];
        int v1 = (w1 < MWORDS) ? Mask[(size_t)w1 * 32 + lane] : 0;
        int v2 = (w2 < MWORDS) ? Mask[(size_t)w2 * 32 + lane] : 0;
        int v3 = (w3 < MWORDS) ? Mask[(size_t)w3 * 32 + lane] : 0;
        u32 b0 = __ballot_sync(0xffffffffu, v0 != 0);
        u32 b1 = __ballot_sync(0xffffffffu, v1 != 0);
        u32 b2 = __ballot_sync(0xffffffffu, v2 != 0);
        u32 b3 = __ballot_sync(0xffffffffu, v3 != 0);
        if (lane == 0) {
            Mpg[w0] = b0;
            if (w1 < MWORDS) Mpg[w1] = b1;
            if (w2 < MWORDS) Mpg[w2] = b2;
            if (w3 < MWORDS) Mpg[w3] = b3;
        }
    }
}

// ---------------------------------------------------------------------------
// tf32 GEMM for QKV projections (fused over grid.z): C = A[M,512] @ W[512,512].
// Epilogue stores tf32-ROUNDED floats (flash consumes raw bits).
// ---------------------------------------------------------------------------
#define LDA 36
#define LDB 136

__global__ __launch_bounds__(256) void gemm_qkv_tf32(
    const float* __restrict__ A0, const float* __restrict__ A1,
    const float* __restrict__ A2,
    const float* __restrict__ W0, const float* __restrict__ W1,
    const float* __restrict__ W2,
    float* __restrict__ C0, float* __restrict__ C1, float* __restrict__ C2)
{
    __shared__ u32 As[128 * LDA];
    __shared__ u32 Bs[32 * LDB];

    const float* A; const float* Bw; float* C;
    if (blockIdx.z == 0)      { A = A0; Bw = W0; C = C0; }
    else if (blockIdx.z == 1) { A = A1; Bw = W1; C = C1; }
    else                      { A = A2; Bw = W2; C = C2; }

    const int tid  = threadIdx.x;
    const int lane = tid & 31;
    const int w    = tid >> 5;
    const int g    = lane >> 2;
    const int c    = lane & 3;
    const int wm   = w & 3;
    const int wn   = w >> 2;
    const int bn = blockIdx.x * 128;
    const int bm = blockIdx.y * 128;

    const int arow = tid >> 1;
    const int akg  = (tid & 1) * 16;
    const int brow = tid >> 3;
    const int bcg  = (tid & 7) * 16;

    float acc[2][8][4];
#pragma unroll
    for (int mt = 0; mt < 2; ++mt)
#pragma unroll
        for (int nt = 0; nt < 8; ++nt)
#pragma unroll
            for (int j = 0; j < 4; ++j) acc[mt][nt][j] = 0.f;

    for (int k0 = 0; k0 < 512; k0 += 32) {
        {
            const float* Ap = A + (size_t)(bm + arow) * 512 + k0 + akg;
#pragma unroll
            for (int i = 0; i < 4; ++i) {
                float4 v = *(const float4*)(Ap + 4 * i);
                *(uint4*)&As[arow * LDA + akg + 4 * i] =
                    make_uint4(to_tf32(v.x), to_tf32(v.y), to_tf32(v.z), to_tf32(v.w));
            }
        }
        {
            const float* Bp = Bw + (size_t)(k0 + brow) * 512 + bn + bcg;
#pragma unroll
            for (int i = 0; i < 4; ++i) {
                float4 v = *(const float4*)(Bp + 4 * i);
                *(uint4*)&Bs[brow * LDB + bcg + 4 * i] =
                    make_uint4(to_tf32(v.x), to_tf32(v.y), to_tf32(v.z), to_tf32(v.w));
            }
        }
        __syncthreads();

#pragma unroll
        for (int ks = 0; ks < 4; ++ks) {
            u32 a[2][4];
#pragma unroll
            for (int mt = 0; mt < 2; ++mt) {
                int base = (32 * wm + 16 * mt + g) * LDA + ks * 8 + c;
                a[mt][0] = As[base];
                a[mt][1] = As[base + 8 * LDA];
                a[mt][2] = As[base + 4];
                a[mt][3] = As[base + 8 * LDA + 4];
            }
#pragma unroll
            for (int nt = 0; nt < 8; ++nt) {
                u32 b0 = Bs[(ks * 8 + c)     * LDB + 64 * wn + nt * 8 + g];
                u32 b1 = Bs[(ks * 8 + c + 4) * LDB + 64 * wn + nt * 8 + g];
#pragma unroll
                for (int mt = 0; mt < 2; ++mt)
                    mma_tf32(acc[mt][nt][0], acc[mt][nt][1], acc[mt][nt][2], acc[mt][nt][3],
                             a[mt][0], a[mt][1], a[mt][2], a[mt][3], b0, b1);
            }
        }
        __syncthreads();
    }

#pragma unroll
    for (int mt = 0; mt < 2; ++mt) {
        float* Cp0 = C + (size_t)(bm + 32 * wm + 16 * mt + g) * 512 + bn + 64 * wn;
        float* Cp1 = Cp0 + (size_t)8 * 512;
#pragma unroll
        for (int nt = 0; nt < 8; ++nt) {
            *(uint2*)(Cp0 + nt * 8 + 2 * c) =
                make_uint2(to_tf32(acc[mt][nt][0]), to_tf32(acc[mt][nt][1]));
            *(uint2*)(Cp1 + nt * 8 + 2 * c) =
                make_uint2(to_tf32(acc[mt][nt][2]), to_tf32(acc[mt][nt][3]));
        }
    }
}

// ---------------------------------------------------------------------------
// SGEMM fp32 (FFMA2) — final Wo projection (accuracy margin).
// ---------------------------------------------------------------------------
__global__ __launch_bounds__(256) void sgemm_k512(
    const float* __restrict__ A, const float* __restrict__ Bw,
    float* __restrict__ C)
{
    __shared__ float Asf[8][128];
    __shared__ float Bsf[8][128];

    const int tid = threadIdx.x;
    const int tx = tid & 15;
    const int ty = tid >> 4;
    const int bn = blockIdx.x * 128;
    const int bm = blockIdx.y * 128;

    const int arow = tid >> 1;
    const int acol = (tid & 1) << 2;
    const int brow = tid >> 5;
    const int bcol = (tid & 31) << 2;

    const float* Ap = A + (size_t)(bm + arow) * 512 + acol;
    const float* Bp = Bw + (size_t)brow * 512 + bn + bcol;

    ull acc2[8][4];
#pragma unroll
    for (int i = 0; i < 8; ++i)
#pragma unroll
        for (int j = 0; j < 4; ++j) acc2[i][j] = 0ull;

    for (int k0 = 0; k0 < 512; k0 += 8) {
        float4 av = *(const float4*)Ap;  Ap += 8;
        float4 bv = *(const float4*)Bp;  Bp += 8 * 512;
        Asf[acol + 0][arow] = av.x;
        Asf[acol + 1][arow] = av.y;
        Asf[acol + 2][arow] = av.z;
        Asf[acol + 3][arow] = av.w;
        *(float4*)&Bsf[brow][bcol] = bv;
        __syncthreads();
#pragma unroll
        for (int kk = 0; kk < 8; ++kk) {
            float ar[8];
            *(float4*)(ar)     = *(const float4*)&Asf[kk][ty * 8];
            *(float4*)(ar + 4) = *(const float4*)&Asf[kk][ty * 8 + 4];
            ulonglong2 b01 = *(const ulonglong2*)&Bsf[kk][tx * 8];
            ulonglong2 b23 = *(const ulonglong2*)&Bsf[kk][tx * 8 + 4];
#pragma unroll
            for (int i = 0; i < 8; ++i) {
                ull ap = pk2(ar[i], ar[i]);
                acc2[i][0] = f2fma(ap, b01.x, acc2[i][0]);
                acc2[i][1] = f2fma(ap, b01.y, acc2[i][1]);
                acc2[i][2] = f2fma(ap, b23.x, acc2[i][2]);
                acc2[i][3] = f2fma(ap, b23.y, acc2[i][3]);
            }
        }
        __syncthreads();
    }

    float* Cp = C + (size_t)(bm + ty * 8) * 512 + bn + tx * 8;
#pragma unroll
    for (int i = 0; i < 8; ++i) {
        float c0, c1, c2, c3, c4, c5, c6, c7;
        upk(acc2[i][0], c0, c1); upk(acc2[i][1], c2, c3);
        upk(acc2[i][2], c4, c5); upk(acc2[i][3], c6, c7);
        *(float4*)(Cp + (size_t)i * 512)     = make_float4(c0, c1, c2, c3);
        *(float4*)(Cp + (size_t)i * 512 + 4) = make_float4(c4, c5, c6, c7);
    }
}

// ---------------------------------------------------------------------------
// Flash attention v10:
//  - tf32 mma, Bq=128, 256 threads = 8 warps, warp tile m16 x n64
//  - permuted K (slot(k)=((k&3)<<1)|(k>>2) in 8-groups): S accumulator regs
//    ARE the PV A-fragments (verified) -> zero shuffles; V natural [k][d]
//  - mask from PRE-PACKED bits (Mpg): 4 u32 loads per thread per iter
//  - cp.async DOUBLE-buffered K/V: load latency off the critical path
// smem: Qs[128][68] + 2*K[64][68] + 2*V[64][72] = 106496 B -> 2 CTAs/SM,
// 16 warps/SM, regs capped at 128 (no spills: s32+o32+~40 live).
// ---------------------------------------------------------------------------
#define LDQ 68
#define LDK 68
#define LDV 72
#define QW   (128 * LDQ)
#define KBW  (64 * LDK)
#define VBW  (64 * LDV)
#define KOFF QW
#define VOFF (QW + 2 * KBW)
#define FSMEM ((QW + 2 * KBW + 2 * VBW) * 4)   // 106496

__global__ void __launch_bounds__(256, 2) flash_attn(
    const float* __restrict__ Q, const float* __restrict__ K,
    const float* __restrict__ V, float* __restrict__ O)
{
    extern __shared__ u32 dsm[];
    u32* Qs = dsm;
    const u32 sbase = (u32)__cvta_generic_to_shared(dsm);

    const int tid  = threadIdx.x;
    const int lane = tid & 31;
    const int w    = tid >> 5;       // warp 0..7 -> q rows [16w, 16w+16)
    const int g    = lane >> 2;
    const int c    = lane & 3;
    const int q0 = blockIdx.x * 128;
    const int h  = blockIdx.y;
    const int b  = blockIdx.z;

    // K/V coop load: 64 rows, 4 threads per row (16 floats each)
    const int r2 = tid >> 2;
    const int qt = (tid & 3) * 16;
    const int prow = (r2 & 56) | (((r2 & 3) << 1) | ((r2 & 7) >> 2));

    const float* ksrc0 = K + ((size_t)(b * Ss + r2)) * HDv + h * 64 + qt;
    const float* vsrc0 = V + ((size_t)(b * Ss + r2)) * HDv + h * 64 + qt;
    const u32 kdst0 = sbase + (KOFF + prow * LDK + qt) * 4;
    const u32 vdst0 = sbase + (VOFF + r2 * LDV + qt) * 4;

    // Q tile: raw bit copy (already tf32-valued); 2 threads per row
    {
        const int r = tid >> 1;
        const int half = (tid & 1) * 32;
        const float* qp = Q + (size_t)(b * Ss + q0 + r) * HDv + h * 64 + half;
#pragma unroll
        for (int i = 0; i < 8; ++i)
            *(uint4*)&Qs[r * LDQ + half + 4 * i] = *(const uint4*)(qp + 4 * i);
    }

    // prologue: issue K/V tile 0 into buffer 0
#pragma unroll
    for (int j = 0; j < 4; ++j) {
        cpa16(kdst0 + 16 * j, ksrc0 + 4 * j);
        cpa16(vdst0 + 16 * j, vsrc0 + 4 * j);
    }
    cpa_commit();

    float m_[2], l_[2];
    float o[8][4];
    m_[0] = m_[1] = -CUDART_INF_F;
    l_[0] = l_[1] = 0.f;
#pragma unroll
    for (int nt = 0; nt < 8; ++nt)
#pragma unroll
        for (int j = 0; j < 4; ++j) o[nt][j] = 0.f;

    // packed-mask word bases (Ss/32 = 128 words per q-row)
    const size_t mw0 = ((size_t)((b * Hh + h) * Ss + q0 + 16 * w + g)) * 128;
    const size_t mw1 = mw0 + (size_t)8 * 128;

    for (int it = 0; it < Ss / 64; ++it) {
        const int buf = it & 1;
        __syncthreads();   // prev compute (used buf^1) done; Q store covered iter 0

        // mask words for this tile (4 small loads; land during wait+sync)
        u32 mwa0 = Mpg[mw0 + it * 2], mwa1 = Mpg[mw0 + it * 2 + 1];
        u32 mwb0 = Mpg[mw1 + it * 2], mwb1 = Mpg[mw1 + it * 2 + 1];

        // issue next K/V tile into the other buffer
        if (it + 1 < Ss / 64) {
            const float* kp = ksrc0 + (size_t)(it + 1) * 64 * HDv;
            const float* vp = vsrc0 + (size_t)(it + 1) * 64 * HDv;
            const u32 kd = kdst0 + (buf ^ 1) * KBW * 4;
            const u32 vd = vdst0 + (buf ^ 1) * VBW * 4;
#pragma unroll
            for (int j = 0; j < 4; ++j) {
                cpa16(kd + 16 * j, kp + 4 * j);
                cpa16(vd + 16 * j, vp + 4 * j);
            }
        }
        cpa_commit();
        cpa_wait1();       // current tile arrived
        __syncthreads();   // visible to all warps

        const u32* Kc = dsm + KOFF + buf * KBW;
        const u32* Vc = dsm + VOFF + buf * VBW;

        // ---- S = Q K^T (columns in permuted slot order) ----
        float s[8][4];
#pragma unroll
        for (int nt = 0; nt < 8; ++nt)
#pragma unroll
            for (int j = 0; j < 4; ++j) s[nt][j] = 0.f;

#pragma unroll
        for (int ks = 0; ks < 8; ++ks) {
            int base = (16 * w + g) * LDQ + ks * 8 + c;
            u32 a0 = Qs[base];
            u32 a1 = Qs[base + 8 * LDQ];
            u32 a2 = Qs[base + 4];
            u32 a3 = Qs[base + 8 * LDQ + 4];
#pragma unroll
            for (int nt = 0; nt < 8; ++nt) {
                u32 b0 = Kc[(nt * 8 + g) * LDK + ks * 8 + c];
                u32 b1 = Kc[(nt * 8 + g) * LDK + ks * 8 + c + 4];
                mma_tf32(s[nt][0], s[nt][1], s[nt][2], s[nt][3],
                         a0, a1, a2, a3, b0, b1);
            }
        }

        // ---- online softmax; P (tf32-rounded) stays in s[] ----
        // element j=2sb   -> row (g or g+8), true k = nt*8 + c
        // element j=2sb+1 -> row (g or g+8), true k = nt*8 + c + 4
#pragma unroll
        for (int sb = 0; sb < 2; ++sb) {
            const int j0 = 2 * sb, j1 = 2 * sb + 1;
            const u32 wa = sb ? mwb0 : mwa0;   // cols [it*64, +32)
            const u32 wb = sb ? mwb1 : mwa1;   // cols [it*64+32, +32)
            float mt_ = -CUDART_INF_F;
#pragma unroll
            for (int nt = 0; nt < 8; ++nt) {
                const u32 word = (nt < 4) ? wa : wb;
                const int sh = ((nt & 3) * 8) + c;
                s[nt][j0] = ((word >> sh) & 1u)       ? -1e10f : s[nt][j0] * 0.125f;
                s[nt][j1] = ((word >> (sh + 4)) & 1u) ? -1e10f : s[nt][j1] * 0.125f;
                mt_ = fmaxf(mt_, fmaxf(s[nt][j0], s[nt][j1]));
            }
            mt_ = fmaxf(mt_, __shfl_xor_sync(0xffffffffu, mt_, 1));
            mt_ = fmaxf(mt_, __shfl_xor_sync(0xffffffffu, mt_, 2));
            float mnew = fmaxf(m_[sb], mt_);
            float corr = __expf(m_[sb] - mnew);
            m_[sb] = mnew;
            float rs = 0.f;
#pragma unroll
            for (int nt = 0; nt < 8; ++nt) {
                float p0 = __uint_as_float(to_tf32(__expf(s[nt][j0] - mnew)));
                float p1 = __uint_as_float(to_tf32(__expf(s[nt][j1] - mnew)));
                rs += p0 + p1;
                s[nt][j0] = p0;
                s[nt][j1] = p1;
                o[nt][j0] *= corr;
                o[nt][j1] *= corr;
            }
            rs += __shfl_xor_sync(0xffffffffu, rs, 1);
            rs += __shfl_xor_sync(0xffffffffu, rs, 2);
            l_[sb] = l_[sb] * corr + rs;
        }

        // ---- O += P V : A-fragments straight from s[] (a0,a1,a2,a3 = d0,d2,d1,d3) ----
#pragma unroll
        for (int kc = 0; kc < 8; ++kc) {
#pragma unroll
            for (int nt = 0; nt < 8; ++nt) {
                u32 b0 = Vc[(kc * 8 + c)     * LDV + nt * 8 + g];
                u32 b1 = Vc[(kc * 8 + c + 4) * LDV + nt * 8 + g];
                mma_tf32(o[nt][0], o[nt][1], o[nt][2], o[nt][3],
                         __float_as_uint(s[kc][0]), __float_as_uint(s[kc][2]),
                         __float_as_uint(s[kc][1]), __float_as_uint(s[kc][3]),
                         b0, b1);
            }
        }
    }

    // normalize + write
    const float inv0 = 1.f / l_[0];
    const float inv1 = 1.f / l_[1];
    float* op0 = O + (size_t)(b * Ss + q0 + 16 * w + g) * HDv + h * 64;
    float* op1 = op0 + (size_t)8 * HDv;
#pragma unroll
    for (int nt = 0; nt < 8; ++nt) {
        *(float2*)(op0 + nt * 8 + 2 * c) = make_float2(o[nt][0] * inv0, o[nt][1] * inv0);
        *(float2*)(op1 + nt * 8 + 2 * c) = make_float2(o[nt][2] * inv1, o[nt][3] * inv1);
    }
}

// ---------------------------------------------------------------------------
// Launch
// ---------------------------------------------------------------------------
extern "C" void kernel_launch(void* const* d_in, const int* in_sizes, int n_in,
                              void* d_out, int out_size)
{
    (void)in_sizes; (void)n_in; (void)out_size;
    const float* queries = (const float*)d_in[0];
    const float* keys    = (const float*)d_in[1];
    const float* values  = (const float*)d_in[2];
    const int*   mask    = (const int*)d_in[3];
    const float* Wq = (const float*)d_in[4];
    const float* Wk = (const float*)d_in[5];
    const float* Wv = (const float*)d_in[6];
    const float* Wo = (const float*)d_in[7];

    void *qp, *kp, *vp, *op;
    cudaGetSymbolAddress(&qp, Qg);
    cudaGetSymbolAddress(&kp, Kg);
    cudaGetSymbolAddress(&vp, Vg);
    cudaGetSymbolAddress(&op, Og);

    cudaFuncSetAttribute(flash_attn,
                         cudaFuncAttributeMaxDynamicSharedMemorySize, FSMEM);

    dim3 gg(512 / 128, (Bb * Ss) / 128);        // (4, 64)
    dim3 gq(512 / 128, (Bb * Ss) / 128, 3);     // fused QKV

    pack_mask<<<1024, 256>>>(mask);

    gemm_qkv_tf32<<<gq, 256>>>(queries, keys, values, Wq, Wk, Wv,
                               (float*)qp, (float*)kp, (float*)vp);

    flash_attn<<<dim3(Ss / 128, Hh, Bb), 256, FSMEM>>>(
        (const float*)qp, (const float*)kp, (const float*)vp, (float*)op);

    sgemm_k512<<<gg, 256>>>((const float*)op, Wo, (float*)d_out);
}